// round 12
// baseline (speedup 1.0000x reference)
#include <cuda_runtime.h>
#include <cuda_fp16.h>

// Problem: B=2, 128^3 grid, C=3, 7 scaling-and-squaring steps.
#define D 128
#define DMASK 127
#define D3 (D * D * D)          // 2097152
#define NVOX (2 * D3)           // 4194304 voxels (B=2)
#define NT 256
#define NB (NVOX / NT)

// fp32 SoA ping-pong (value path, full precision), 48 MB each.
__device__ float  gA[3 * NVOX];
__device__ float  gB[3 * NVOX];
// fp16 mirrors (gather-tap path), 24 MB each. Same SoA layout.
__device__ __half gHA[3 * NVOX];
__device__ __half gHB[3 * NVOX];

// ---------------------------------------------------------------------------
// Transpose + scale: AoS dvf -> SoA fp32 in gA and fp16 mirror in gHA, * 2^-7.
// ---------------------------------------------------------------------------
__global__ __launch_bounds__(256) void transpose_scale_kernel(
    const float4* __restrict__ in4)
{
    const int i = blockIdx.x * 256 + threadIdx.x;        // i < 3*NVOX/4
    const float s = 1.0f / 128.0f;                       // 2^-7, exact
    float4 v = in4[i];
    float vals[4] = {v.x, v.y, v.z, v.w};
    const int f = 4 * i;
    #pragma unroll
    for (int j = 0; j < 4; j++) {
        const int ff  = f + j;
        const int vox = ff / 3;
        const int c   = ff - 3 * vox;
        const float sv = s * vals[j];
        gA[c * NVOX + vox]  = sv;
        gHA[c * NVOX + vox] = __float2half(sv);
    }
}

// ---------------------------------------------------------------------------
// One squaring step. Centers/accumulation/output in fp32; the 24 gather taps
// read the fp16 mirror (half the L1 lines + half the return bytes).
// SRC: 1 = (gA,gHA), 2 = (gB,gHB).  DST: 0 = AoS d_out, 1/2 = fp32+fp16 pair.
// ---------------------------------------------------------------------------
template <int SRC, int DST>
__global__ __launch_bounds__(NT) void step_soa_kernel(
    float* __restrict__ ext_out)
{
    const float*  __restrict__ sx = (SRC == 1) ? gA : gB;
    const float*  __restrict__ sy = sx + NVOX;
    const float*  __restrict__ sz = sx + 2 * NVOX;
    const __half* __restrict__ hx = (SRC == 1) ? gHA : gHB;
    const __half* __restrict__ hy = hx + NVOX;
    const __half* __restrict__ hz = hx + 2 * NVOX;

    const int idx = blockIdx.x * NT + threadIdx.x;

    // Center displacement (coalesced, fp32 — exact value path).
    const float vx = __ldg(sx + idx);
    const float vy = __ldg(sy + idx);
    const float vz = __ldg(sz + idx);

    const int z = idx & DMASK;
    const int y = (idx >> 7) & DMASK;
    const int x = (idx >> 14) & DMASK;
    const int bbase = (idx >> 21) * D3;

    const float lx = (float)x + vx;
    const float ly = (float)y + vy;
    const float lz = (float)z + vz;

    const float fx = floorf(lx), fy = floorf(ly), fz = floorf(lz);
    const float wx1 = lx - fx, wy1 = ly - fy, wz1 = lz - fz;
    const float wx0 = 1.0f - wx1, wy0 = 1.0f - wy1, wz0 = 1.0f - wz1;

    const int ix = (int)fx, iy = (int)fy, iz = (int)fz;

    // Clip corner indices; weights stay unclipped (matches reference).
    const int ix0 = min(max(ix,     0), DMASK);
    const int ix1 = min(max(ix + 1, 0), DMASK);
    const int iy0 = min(max(iy,     0), DMASK);
    const int iy1 = min(max(iy + 1, 0), DMASK);
    const int iz0 = min(max(iz,     0), DMASK);
    const int iz1 = min(max(iz + 1, 0), DMASK);

    const int X0 = bbase + (ix0 << 14);
    const int X1 = bbase + (ix1 << 14);
    const int Y0 = iy0 << 7;
    const int Y1 = iy1 << 7;

    const float w00 = wx0 * wy0;
    const float w01 = wx0 * wy1;
    const float w10 = wx1 * wy0;
    const float w11 = wx1 * wy1;

    float ax = 0.0f, ay = 0.0f, az = 0.0f;

    #define CORNER(W, LIN)                                                    \
        do {                                                                  \
            const float w_ = (W);                                             \
            const int   l_ = (LIN);                                           \
            ax = fmaf(w_, __half2float(__ldg(hx + l_)), ax);                  \
            ay = fmaf(w_, __half2float(__ldg(hy + l_)), ay);                  \
            az = fmaf(w_, __half2float(__ldg(hz + l_)), az);                  \
        } while (0)

    CORNER(w00 * wz0, X0 + Y0 + iz0);
    CORNER(w00 * wz1, X0 + Y0 + iz1);
    CORNER(w01 * wz0, X0 + Y1 + iz0);
    CORNER(w01 * wz1, X0 + Y1 + iz1);
    CORNER(w10 * wz0, X1 + Y0 + iz0);
    CORNER(w10 * wz1, X1 + Y0 + iz1);
    CORNER(w11 * wz0, X1 + Y1 + iz0);
    CORNER(w11 * wz1, X1 + Y1 + iz1);
    #undef CORNER

    const float ox = vx + ax;
    const float oy = vy + ay;
    const float oz = vz + az;

    if (DST == 0) {
        // Final step: AoS float3 into d_out (no mirror needed).
        float* o = ext_out + 3 * idx;
        o[0] = ox; o[1] = oy; o[2] = oz;
    } else {
        float*  dx = (DST == 1) ? gA : gB;
        __half* hd = (DST == 1) ? gHA : gHB;
        dx[idx]            = ox;
        dx[NVOX + idx]     = oy;
        dx[2 * NVOX + idx] = oz;
        hd[idx]            = __float2half(ox);
        hd[NVOX + idx]     = __float2half(oy);
        hd[2 * NVOX + idx] = __float2half(oz);
    }
}

extern "C" void kernel_launch(void* const* d_in, const int* in_sizes, int n_in,
                              void* d_out, int out_size)
{
    const float4* dvf4 = (const float4*)d_in[0];
    float* out = (float*)d_out;

    // AoS dvf -> scaled SoA fp32 + fp16 mirror (ddf0 = dvf * 2^-7, exact).
    transpose_scale_kernel<<<(3 * NVOX / 4) / 256, 256>>>(dvf4);

    // 7 squaring steps, ping-pong; final step writes AoS into d_out.
    step_soa_kernel<1, 2><<<NB, NT>>>(nullptr);  // 1: A -> B
    step_soa_kernel<2, 1><<<NB, NT>>>(nullptr);  // 2: B -> A
    step_soa_kernel<1, 2><<<NB, NT>>>(nullptr);  // 3: A -> B
    step_soa_kernel<2, 1><<<NB, NT>>>(nullptr);  // 4: B -> A
    step_soa_kernel<1, 2><<<NB, NT>>>(nullptr);  // 5: A -> B
    step_soa_kernel<2, 1><<<NB, NT>>>(nullptr);  // 6: B -> A
    step_soa_kernel<1, 0><<<NB, NT>>>(out);      // 7: A -> d_out
}

// round 14
// speedup vs baseline: 1.0318x; 1.0318x over previous
#include <cuda_runtime.h>
#include <cuda_fp16.h>

// Problem: B=2, 128^3 grid, C=3, 7 scaling-and-squaring steps.
#define D 128
#define DMASK 127
#define D3 (D * D * D)          // 2097152
#define NVOX (2 * D3)           // 4194304 voxels (B=2)
#define NV3 (3 * NVOX)
#define NT 256
#define NB (NVOX / NT)

// fp32 SoA ping-pong (exact value path), 48 MB each. [comp][b*D3 + x*D*D + y*D + z]
__device__ float gA[NV3];
__device__ float gB[NV3];
// fp16 shifted-pair mirrors: logical P[i] = (f16[i], f16[i+1]) at gP[1+i].
// gP[0] is a front pad so the "previous .y" store at i=0 stays in bounds.
// Device statics are zero-initialized, so never-written .y slots read 0.0f.
__device__ __half2 gPA[NV3 + 1];
__device__ __half2 gPB[NV3 + 1];

// Write value h into both half-slots owned by logical index L:
//   P[L].x  -> halves[2L+2],   P[L-1].y -> halves[2L+1]
__device__ __forceinline__ void pair_store(__half* hbase, int L, __half h)
{
    hbase[2 * L + 2] = h;
    hbase[2 * L + 1] = h;
}

// ---------------------------------------------------------------------------
// Transpose + scale: AoS dvf -> fp32 SoA gA + fp16 pair mirror gPA, * 2^-7.
// ---------------------------------------------------------------------------
__global__ __launch_bounds__(256) void transpose_scale_kernel(
    const float4* __restrict__ in4)
{
    const int i = blockIdx.x * 256 + threadIdx.x;        // i < NV3/4
    const float s = 1.0f / 128.0f;                       // 2^-7, exact
    float4 v = in4[i];
    float vals[4] = {v.x, v.y, v.z, v.w};
    const int f = 4 * i;
    __half* hp = (__half*)gPA;
    #pragma unroll
    for (int j = 0; j < 4; j++) {
        const int ff  = f + j;
        const int vox = ff / 3;
        const int c   = ff - 3 * vox;
        const float sv = s * vals[j];
        const int L = c * NVOX + vox;
        gA[L] = sv;
        pair_store(hp, L, __float2half(sv));
    }
}

// ---------------------------------------------------------------------------
// One squaring step. Centers/accumulation/output fp32; the 8 corners are
// fetched as 12 half2 pair-loads (one per xy-corner per component) covering
// both z taps at once. z-clip (iz1==iz0) is handled by folding wz1 into wz0
// so the .y lane gets weight 0.
// SRC: 1=(gA,gPA), 2=(gB,gPB). DST: 0=AoS d_out, 1/2 = pair.
// ---------------------------------------------------------------------------
template <int SRC, int DST>
__global__ __launch_bounds__(NT) void step_pair_kernel(
    float* __restrict__ ext_out)
{
    const float* __restrict__ sx = (SRC == 1) ? gA : gB;
    const float* __restrict__ sy = sx + NVOX;
    const float* __restrict__ sz = sx + 2 * NVOX;
    const __half2* __restrict__ P = ((SRC == 1) ? gPA : gPB) + 1;  // logical P[i]

    const int idx = blockIdx.x * NT + threadIdx.x;

    // Center displacement (coalesced, fp32 — exact value path).
    const float vx = __ldg(sx + idx);
    const float vy = __ldg(sy + idx);
    const float vz = __ldg(sz + idx);

    const int z = idx & DMASK;
    const int y = (idx >> 7) & DMASK;
    const int x = (idx >> 14) & DMASK;
    const int bbase = (idx >> 21) * D3;

    const float lx = (float)x + vx;
    const float ly = (float)y + vy;
    const float lz = (float)z + vz;

    const float fx = floorf(lx), fy = floorf(ly), fz = floorf(lz);
    const float wx1 = lx - fx, wy1 = ly - fy;
    float wz1 = lz - fz;
    const float wx0 = 1.0f - wx1, wy0 = 1.0f - wy1;
    float wz0 = 1.0f - wz1;

    const int ix = (int)fx, iy = (int)fy, iz = (int)fz;

    // Clip corner indices; weights stay unclipped (matches reference).
    const int ix0 = min(max(ix,     0), DMASK);
    const int ix1 = min(max(ix + 1, 0), DMASK);
    const int iy0 = min(max(iy,     0), DMASK);
    const int iy1 = min(max(iy + 1, 0), DMASK);
    const int iz0 = min(max(iz,     0), DMASK);
    const int iz1 = min(max(iz + 1, 0), DMASK);

    // If clipped so iz1 == iz0, both z taps read the same voxel: fold the
    // wz1 weight onto the .x lane and zero the .y lane (reads 0*finite).
    if (iz1 == iz0) { wz0 += wz1; wz1 = 0.0f; }

    const int X0 = bbase + (ix0 << 14);
    const int X1 = bbase + (ix1 << 14);
    const int Y0 = iy0 << 7;
    const int Y1 = iy1 << 7;

    // 4 xy-corner linear indices (z handled by the pair).
    const int l00 = X0 + Y0 + iz0;
    const int l01 = X0 + Y1 + iz0;
    const int l10 = X1 + Y0 + iz0;
    const int l11 = X1 + Y1 + iz0;

    const float w00 = wx0 * wy0;
    const float w01 = wx0 * wy1;
    const float w10 = wx1 * wy0;
    const float w11 = wx1 * wy1;
    const float w000 = w00 * wz0, w001 = w00 * wz1;
    const float w010 = w01 * wz0, w011 = w01 * wz1;
    const float w100 = w10 * wz0, w101 = w10 * wz1;
    const float w110 = w11 * wz0, w111 = w11 * wz1;

    float ax, ay, az;

    #define GATHER_COMP(CO, ACC)                                              \
        do {                                                                  \
            const float2 t00 = __half22float2(__ldg(P + (CO) + l00));         \
            const float2 t01 = __half22float2(__ldg(P + (CO) + l01));         \
            const float2 t10 = __half22float2(__ldg(P + (CO) + l10));         \
            const float2 t11 = __half22float2(__ldg(P + (CO) + l11));         \
            float a = w000 * t00.x;                                           \
            a = fmaf(w001, t00.y, a);                                         \
            a = fmaf(w010, t01.x, a);                                         \
            a = fmaf(w011, t01.y, a);                                         \
            a = fmaf(w100, t10.x, a);                                         \
            a = fmaf(w101, t10.y, a);                                         \
            a = fmaf(w110, t11.x, a);                                         \
            a = fmaf(w111, t11.y, a);                                         \
            ACC = a;                                                          \
        } while (0)

    GATHER_COMP(0,        ax);
    GATHER_COMP(NVOX,     ay);
    GATHER_COMP(2 * NVOX, az);
    #undef GATHER_COMP

    const float ox = vx + ax;
    const float oy = vy + ay;
    const float oz = vz + az;

    if (DST == 0) {
        // Final step: AoS float3 into d_out (no mirror maintenance).
        float* o = ext_out + 3 * idx;
        o[0] = ox; o[1] = oy; o[2] = oz;
    } else {
        float* dx = (DST == 1) ? gA : gB;
        dx[idx]            = ox;
        dx[NVOX + idx]     = oy;
        dx[2 * NVOX + idx] = oz;
        __half* hp = (__half*)((DST == 1) ? gPA : gPB);
        pair_store(hp, idx,            __float2half(ox));
        pair_store(hp, NVOX + idx,     __float2half(oy));
        pair_store(hp, 2 * NVOX + idx, __float2half(oz));
    }
}

extern "C" void kernel_launch(void* const* d_in, const int* in_sizes, int n_in,
                              void* d_out, int out_size)
{
    const float4* dvf4 = (const float4*)d_in[0];
    float* out = (float*)d_out;

    // AoS dvf -> scaled fp32 SoA + fp16 pair mirror (ddf0 = dvf * 2^-7, exact).
    transpose_scale_kernel<<<(NV3 / 4) / 256, 256>>>(dvf4);

    // 7 squaring steps, ping-pong; final step writes AoS into d_out.
    step_pair_kernel<1, 2><<<NB, NT>>>(nullptr);  // 1: A -> B
    step_pair_kernel<2, 1><<<NB, NT>>>(nullptr);  // 2: B -> A
    step_pair_kernel<1, 2><<<NB, NT>>>(nullptr);  // 3: A -> B
    step_pair_kernel<2, 1><<<NB, NT>>>(nullptr);  // 4: B -> A
    step_pair_kernel<1, 2><<<NB, NT>>>(nullptr);  // 5: A -> B
    step_pair_kernel<2, 1><<<NB, NT>>>(nullptr);  // 6: B -> A
    step_pair_kernel<1, 0><<<NB, NT>>>(out);      // 7: A -> d_out
}

// round 16
// speedup vs baseline: 1.7695x; 1.7149x over previous
#include <cuda_runtime.h>
#include <cuda_fp16.h>

// Problem: B=2, 128^3 grid, C=3, 7 scaling-and-squaring steps.
#define D 128
#define DMASK 127
#define D3 (D * D * D)          // 2097152
#define NVOX (2 * D3)           // 4194304 voxels (B=2)
#define NV3 (3 * NVOX)
#define NT 256
#define NB (NVOX / NT)

// fp16 shifted-pair ping-pong buffers (the ONLY state), 24 MB each.
// Logical P[i] = (h[i], h[i+1]) lives at gP[1+i]; gP[0] is a front pad.
// halves view: h[L] as .x at halves[2L+2], as .y at halves[2L+1].
__device__ __half2 gPA[NV3 + 1];
__device__ __half2 gPB[NV3 + 1];

// ---------------------------------------------------------------------------
// Shared-exchange pair store: each thread stores (own, next) as one half2.
// Block-edge threads complete the boundary word with disjoint 2-byte stores.
// Call with sh[3][NT] already filled and __syncthreads() done.
// ---------------------------------------------------------------------------
__device__ __forceinline__ void store_pairs(
    __half2* __restrict__ dst2,      // = gP (word base), logical P[i] at dst2[1+i]
    const __half sh[][NT], int tid, int idx,
    __half hx_, __half hy_, __half hz_)
{
    __half* hb = (__half*)dst2;
    if (tid < NT - 1) {
        dst2[1 + idx]            = __halves2half2(hx_, sh[0][tid + 1]);
        dst2[1 + NVOX + idx]     = __halves2half2(hy_, sh[1][tid + 1]);
        dst2[1 + 2 * NVOX + idx] = __halves2half2(hz_, sh[2][tid + 1]);
    } else {
        // Last thread of block: store .x halves only (next block fills .y).
        hb[2 * (idx) + 2]             = hx_;
        hb[2 * (NVOX + idx) + 2]      = hy_;
        hb[2 * (2 * NVOX + idx) + 2]  = hz_;
    }
    if (tid == 0) {
        // First thread of block: complete the previous block's pair (.y slot).
        hb[2 * (idx) + 1]             = hx_;
        hb[2 * (NVOX + idx) + 1]      = hy_;
        hb[2 * (2 * NVOX + idx) + 1]  = hz_;
    }
}

// ---------------------------------------------------------------------------
// Transpose + scale: AoS dvf -> fp16 pair field gPA, * 2^-7 (exact scale).
// ---------------------------------------------------------------------------
__global__ __launch_bounds__(NT) void transpose_scale_kernel(
    const float* __restrict__ in)
{
    __shared__ __half sh[3][NT];
    const int tid = threadIdx.x;
    const int idx = blockIdx.x * NT + tid;
    const float s = 1.0f / 128.0f;                       // 2^-7, exact

    const float* p = in + 3 * idx;
    const __half hx_ = __float2half(s * p[0]);
    const __half hy_ = __float2half(s * p[1]);
    const __half hz_ = __float2half(s * p[2]);

    sh[0][tid] = hx_; sh[1][tid] = hy_; sh[2][tid] = hz_;
    __syncthreads();
    store_pairs(gPA, sh, tid, idx, hx_, hy_, hz_);
}

// ---------------------------------------------------------------------------
// One squaring step, all-fp16 state. Centers from pair .x; 8 corners fetched
// as 12 half2 pair-loads; z-clip handled by folding wz1 into wz0.
// SRC: 1=gPA, 2=gPB.  DST: 0 = AoS fp32 d_out, 1/2 = pair buffer.
// ---------------------------------------------------------------------------
template <int SRC, int DST>
__global__ __launch_bounds__(NT) void step_h_kernel(
    float* __restrict__ ext_out)
{
    const __half2* __restrict__ P = ((SRC == 1) ? gPA : gPB) + 1;  // logical P[i]
    __shared__ __half sh[3][NT];

    const int tid = threadIdx.x;
    const int idx = blockIdx.x * NT + tid;

    // Center displacement: .x lanes of the pair (coalesced 4B loads).
    const float vx = __half2float(__low2half(__ldg(P + idx)));
    const float vy = __half2float(__low2half(__ldg(P + NVOX + idx)));
    const float vz = __half2float(__low2half(__ldg(P + 2 * NVOX + idx)));

    const int z = idx & DMASK;
    const int y = (idx >> 7) & DMASK;
    const int x = (idx >> 14) & DMASK;
    const int bbase = (idx >> 21) * D3;

    const float lx = (float)x + vx;
    const float ly = (float)y + vy;
    const float lz = (float)z + vz;

    const float fx = floorf(lx), fy = floorf(ly), fz = floorf(lz);
    const float wx1 = lx - fx, wy1 = ly - fy;
    float wz1 = lz - fz;
    const float wx0 = 1.0f - wx1, wy0 = 1.0f - wy1;
    float wz0 = 1.0f - wz1;

    const int ix = (int)fx, iy = (int)fy, iz = (int)fz;

    // Clip corner indices; weights stay unclipped (matches reference).
    const int ix0 = min(max(ix,     0), DMASK);
    const int ix1 = min(max(ix + 1, 0), DMASK);
    const int iy0 = min(max(iy,     0), DMASK);
    const int iy1 = min(max(iy + 1, 0), DMASK);
    const int iz0 = min(max(iz,     0), DMASK);
    const int iz1 = min(max(iz + 1, 0), DMASK);

    // If clipped so iz1 == iz0, both z taps read the same voxel: fold the
    // wz1 weight onto the .x lane; the garbage .y lane gets weight 0.
    if (iz1 == iz0) { wz0 += wz1; wz1 = 0.0f; }

    const int X0 = bbase + (ix0 << 14);
    const int X1 = bbase + (ix1 << 14);
    const int Y0 = iy0 << 7;
    const int Y1 = iy1 << 7;

    const int l00 = X0 + Y0 + iz0;
    const int l01 = X0 + Y1 + iz0;
    const int l10 = X1 + Y0 + iz0;
    const int l11 = X1 + Y1 + iz0;

    const float w00 = wx0 * wy0;
    const float w01 = wx0 * wy1;
    const float w10 = wx1 * wy0;
    const float w11 = wx1 * wy1;
    const float w000 = w00 * wz0, w001 = w00 * wz1;
    const float w010 = w01 * wz0, w011 = w01 * wz1;
    const float w100 = w10 * wz0, w101 = w10 * wz1;
    const float w110 = w11 * wz0, w111 = w11 * wz1;

    float ax, ay, az;

    #define GATHER_COMP(CO, ACC)                                              \
        do {                                                                  \
            const float2 t00 = __half22float2(__ldg(P + (CO) + l00));         \
            const float2 t01 = __half22float2(__ldg(P + (CO) + l01));         \
            const float2 t10 = __half22float2(__ldg(P + (CO) + l10));         \
            const float2 t11 = __half22float2(__ldg(P + (CO) + l11));         \
            float a = w000 * t00.x;                                           \
            a = fmaf(w001, t00.y, a);                                         \
            a = fmaf(w010, t01.x, a);                                         \
            a = fmaf(w011, t01.y, a);                                         \
            a = fmaf(w100, t10.x, a);                                         \
            a = fmaf(w101, t10.y, a);                                         \
            a = fmaf(w110, t11.x, a);                                         \
            a = fmaf(w111, t11.y, a);                                         \
            ACC = a;                                                          \
        } while (0)

    GATHER_COMP(0,        ax);
    GATHER_COMP(NVOX,     ay);
    GATHER_COMP(2 * NVOX, az);
    #undef GATHER_COMP

    const float ox = vx + ax;
    const float oy = vy + ay;
    const float oz = vz + az;

    if (DST == 0) {
        // Final step: AoS float3 (fp32) straight into d_out.
        float* o = ext_out + 3 * idx;
        o[0] = ox; o[1] = oy; o[2] = oz;
    } else {
        const __half hx_ = __float2half(ox);
        const __half hy_ = __float2half(oy);
        const __half hz_ = __float2half(oz);
        sh[0][tid] = hx_; sh[1][tid] = hy_; sh[2][tid] = hz_;
        __syncthreads();
        store_pairs((DST == 1) ? gPA : gPB, sh, tid, idx, hx_, hy_, hz_);
    }
}

extern "C" void kernel_launch(void* const* d_in, const int* in_sizes, int n_in,
                              void* d_out, int out_size)
{
    const float* dvf = (const float*)d_in[0];
    float* out = (float*)d_out;

    // AoS dvf -> scaled fp16 pair field (ddf0 = dvf * 2^-7, exact scale).
    transpose_scale_kernel<<<NB, NT>>>(dvf);

    // 7 squaring steps, ping-pong; final step writes AoS fp32 into d_out.
    step_h_kernel<1, 2><<<NB, NT>>>(nullptr);  // 1: A -> B
    step_h_kernel<2, 1><<<NB, NT>>>(nullptr);  // 2: B -> A
    step_h_kernel<1, 2><<<NB, NT>>>(nullptr);  // 3: A -> B
    step_h_kernel<2, 1><<<NB, NT>>>(nullptr);  // 4: B -> A
    step_h_kernel<1, 2><<<NB, NT>>>(nullptr);  // 5: A -> B
    step_h_kernel<2, 1><<<NB, NT>>>(nullptr);  // 6: B -> A
    step_h_kernel<1, 0><<<NB, NT>>>(out);      // 7: A -> d_out
}